// round 5
// baseline (speedup 1.0000x reference)
#include <cuda_runtime.h>
#include <cstdint>

// ---------------------------------------------------------------------------
// GCN layer: out = relu( (A x) @ W + b )  ==  relu( A (x@W) + b )
// Plan:
//   1) CSR build (zero deg -> histogram -> scan -> scatter packed {col,val})
//   2) y = x @ W   (fp32x2 tiled GEMM, R3 version)  -> scratch g_y
//   3) gather: one warp per row, ALL 4 batches per pass (MLP=4 gathers/edge),
//      fused bias+relu. No atomics, no shfl.
// ---------------------------------------------------------------------------

#define C_DIM 128
static constexpr int  N_NODES = 50000;
static constexpr int  B_MAX   = 4;
static constexpr int  E_MAX   = 800000;
static constexpr long Y_ELEMS = (long)B_MAX * N_NODES * C_DIM;

__device__ float                            g_y[Y_ELEMS];      // 102.4 MB
__device__ int                              g_deg[N_NODES];
__device__ int                              g_off[N_NODES + 1];
__device__ int                              g_cur[N_NODES];
__device__ __align__(16) unsigned long long g_ebuf[E_MAX];     // {val:hi, col:lo}

// ---------------------------------------------------------------------------
// f32x2 packed helpers
// ---------------------------------------------------------------------------
__device__ __forceinline__ unsigned long long pack2(float lo, float hi) {
    unsigned long long r;
    asm("mov.b64 %0, {%1, %2};" : "=l"(r) : "f"(lo), "f"(hi));
    return r;
}
__device__ __forceinline__ void unpack2(unsigned long long p, float& lo, float& hi) {
    asm("mov.b64 {%0, %1}, %2;" : "=f"(lo), "=f"(hi) : "l"(p));
}
__device__ __forceinline__ void fma2(unsigned long long& d,
                                     unsigned long long a,
                                     unsigned long long b) {
    asm("fma.rn.f32x2 %0, %1, %2, %0;" : "+l"(d) : "l"(a), "l"(b));
}

// ---------------------------------------------------------------------------
// CSR build
// ---------------------------------------------------------------------------
__global__ void zero_deg_kernel(int n) {
    int i = blockIdx.x * blockDim.x + threadIdx.x;
    if (i < n) g_deg[i] = 0;
}

__global__ void hist_kernel(const int* __restrict__ er, int E) {
    int e = blockIdx.x * blockDim.x + threadIdx.x;
    if (e < E) atomicAdd(&g_deg[er[e]], 1);
}

__global__ void __launch_bounds__(1024) scan_kernel(int N) {
    __shared__ int part[1024];
    const int tid   = threadIdx.x;
    const int chunk = (N + 1023) / 1024;
    const int s = tid * chunk;
    const int e = min(s + chunk, N);

    int sum = 0;
    for (int i = s; i < e; ++i) sum += g_deg[i];
    part[tid] = sum;
    __syncthreads();

    for (int ofs = 1; ofs < 1024; ofs <<= 1) {
        int v = (tid >= ofs) ? part[tid - ofs] : 0;
        __syncthreads();
        part[tid] += v;
        __syncthreads();
    }
    int run = (tid == 0) ? 0 : part[tid - 1];
    for (int i = s; i < e; ++i) {
        g_off[i] = run;
        g_cur[i] = run;
        run += g_deg[i];
    }
    if (s < N && e == N) g_off[N] = run;
}

__global__ void scatter_kernel(const int*   __restrict__ er,
                               const int*   __restrict__ ec,
                               const float* __restrict__ ev,
                               int E) {
    int e = blockIdx.x * blockDim.x + threadIdx.x;
    if (e >= E) return;
    const int pos = atomicAdd(&g_cur[er[e]], 1);
    const unsigned long long rec =
        ((unsigned long long)__float_as_uint(ev[e]) << 32) | (unsigned)ec[e];
    g_ebuf[pos] = rec;
}

// ---------------------------------------------------------------------------
// GEMM: y = x @ W   (R3 version: 128x128 CTA tile, 256 thr, 8x8 micro, fp32x2)
// ---------------------------------------------------------------------------
__global__ void __launch_bounds__(256)
gemm_kernel(const float* __restrict__ x,
            const float* __restrict__ W,
            int total_rows) {
    extern __shared__ float sm[];
    float* As = sm;                 // [128][128]
    float* Ws = sm + 128 * 128;     // [128][128]

    const int  tid  = threadIdx.x;
    const long row0 = (long)blockIdx.x * 128;

    {
        const float4* Wg = reinterpret_cast<const float4*>(W);
        float4*       Wd = reinterpret_cast<float4*>(Ws);
        for (int i = tid; i < 4096; i += 256) Wd[i] = Wg[i];
    }
    {
        const float4* Ag = reinterpret_cast<const float4*>(x);
        float4*       Ad = reinterpret_cast<float4*>(As);
        for (int i = tid; i < 4096; i += 256) {
            const int  r  = i >> 5;
            const int  c4 = i & 31;
            const long gr = row0 + r;
            Ad[i] = (gr < total_rows) ? Ag[gr * 32 + c4]
                                      : make_float4(0.f, 0.f, 0.f, 0.f);
        }
    }
    __syncthreads();

    const int tx = tid & 15;   // cols [tx*8, tx*8+8)
    const int ty = tid >> 4;   // rows [ty*8, ty*8+8)

    unsigned long long acc[8][4];
#pragma unroll
    for (int r = 0; r < 8; ++r)
#pragma unroll
        for (int cp = 0; cp < 4; ++cp) acc[r][cp] = 0ULL;

    const float* a_base = As + ty * 8 * 128;

#pragma unroll 4
    for (int k = 0; k < 128; ++k) {
        const unsigned long long* wp =
            reinterpret_cast<const unsigned long long*>(Ws + k * 128 + tx * 8);
        const unsigned long long w0 = wp[0];
        const unsigned long long w1 = wp[1];
        const unsigned long long w2 = wp[2];
        const unsigned long long w3 = wp[3];
#pragma unroll
        for (int r = 0; r < 8; ++r) {
            const float a = a_base[r * 128 + k];
            const unsigned long long aa = pack2(a, a);
            fma2(acc[r][0], aa, w0);
            fma2(acc[r][1], aa, w1);
            fma2(acc[r][2], aa, w2);
            fma2(acc[r][3], aa, w3);
        }
    }

#pragma unroll
    for (int r = 0; r < 8; ++r) {
        const long gr = row0 + ty * 8 + r;
        if (gr >= total_rows) continue;
        float o[8];
#pragma unroll
        for (int cp = 0; cp < 4; ++cp)
            unpack2(acc[r][cp], o[2 * cp], o[2 * cp + 1]);
        float4* op = reinterpret_cast<float4*>(g_y + gr * C_DIM + tx * 8);
        op[0] = make_float4(o[0], o[1], o[2], o[3]);
        op[1] = make_float4(o[4], o[5], o[6], o[7]);
    }
}

// ---------------------------------------------------------------------------
// Gather: for each row n, ALL batches at once:
//   out[b,n,:] = relu( bias + sum_e val_e * y[b, col_e, :] ),  b = 0..3
// One warp per row, lane owns 4 channels. Per edge: 1 broadcast record LDG +
// 4 independent row LDG.128 (one per batch). Edge loop unrolled x2 -> 8 row
// loads in flight per warp.
// ---------------------------------------------------------------------------
__global__ void __launch_bounds__(256)
gather_kernel(const float* __restrict__ bias,
              float*       __restrict__ out,
              int N) {
    const int lane = threadIdx.x & 31;
    const int warp = threadIdx.x >> 5;

    const float4* y4    = reinterpret_cast<const float4*>(g_y);
    const size_t  bstr  = (size_t)N * 32;            // float4 stride per batch
    const float4  bias4 = __ldg(reinterpret_cast<const float4*>(bias) + lane);

    const int n_base = blockIdx.x * 64 + warp * 8;

#pragma unroll 1
    for (int i = 0; i < 8; ++i) {
        const int n = n_base + i;
        if (n >= N) return;

        const int st = __ldg(&g_off[n]);
        const int en = __ldg(&g_off[n + 1]);

        float4 ac0 = make_float4(0.f, 0.f, 0.f, 0.f);
        float4 ac1 = make_float4(0.f, 0.f, 0.f, 0.f);
        float4 ac2 = make_float4(0.f, 0.f, 0.f, 0.f);
        float4 ac3 = make_float4(0.f, 0.f, 0.f, 0.f);

        int e = st;
        for (; e + 2 <= en; e += 2) {
            const unsigned long long p0 = __ldg(&g_ebuf[e]);
            const unsigned long long p1 = __ldg(&g_ebuf[e + 1]);
            const size_t ba0 = (size_t)(unsigned)(p0 & 0xffffffffu) * 32 + lane;
            const size_t ba1 = (size_t)(unsigned)(p1 & 0xffffffffu) * 32 + lane;
            const float  v0  = __uint_as_float((unsigned)(p0 >> 32));
            const float  v1  = __uint_as_float((unsigned)(p1 >> 32));

            const float4 xa0 = __ldg(y4 + ba0);
            const float4 xa1 = __ldg(y4 + bstr + ba0);
            const float4 xa2 = __ldg(y4 + 2 * bstr + ba0);
            const float4 xa3 = __ldg(y4 + 3 * bstr + ba0);
            const float4 xb0 = __ldg(y4 + ba1);
            const float4 xb1 = __ldg(y4 + bstr + ba1);
            const float4 xb2 = __ldg(y4 + 2 * bstr + ba1);
            const float4 xb3 = __ldg(y4 + 3 * bstr + ba1);

            ac0.x = fmaf(v0, xa0.x, ac0.x); ac0.y = fmaf(v0, xa0.y, ac0.y);
            ac0.z = fmaf(v0, xa0.z, ac0.z); ac0.w = fmaf(v0, xa0.w, ac0.w);
            ac1.x = fmaf(v0, xa1.x, ac1.x); ac1.y = fmaf(v0, xa1.y, ac1.y);
            ac1.z = fmaf(v0, xa1.z, ac1.z); ac1.w = fmaf(v0, xa1.w, ac1.w);
            ac2.x = fmaf(v0, xa2.x, ac2.x); ac2.y = fmaf(v0, xa2.y, ac2.y);
            ac2.z = fmaf(v0, xa2.z, ac2.z); ac2.w = fmaf(v0, xa2.w, ac2.w);
            ac3.x = fmaf(v0, xa3.x, ac3.x); ac3.y = fmaf(v0, xa3.y, ac3.y);
            ac3.z = fmaf(v0, xa3.z, ac3.z); ac3.w = fmaf(v0, xa3.w, ac3.w);

            ac0.x = fmaf(v1, xb0.x, ac0.x); ac0.y = fmaf(v1, xb0.y, ac0.y);
            ac0.z = fmaf(v1, xb0.z, ac0.z); ac0.w = fmaf(v1, xb0.w, ac0.w);
            ac1.x = fmaf(v1, xb1.x, ac1.x); ac1.y = fmaf(v1, xb1.y, ac1.y);
            ac1.z = fmaf(v1, xb1.z, ac1.z); ac1.w = fmaf(v1, xb1.w, ac1.w);
            ac2.x = fmaf(v1, xb2.x, ac2.x); ac2.y = fmaf(v1, xb2.y, ac2.y);
            ac2.z = fmaf(v1, xb2.z, ac2.z); ac2.w = fmaf(v1, xb2.w, ac2.w);
            ac3.x = fmaf(v1, xb3.x, ac3.x); ac3.y = fmaf(v1, xb3.y, ac3.y);
            ac3.z = fmaf(v1, xb3.z, ac3.z); ac3.w = fmaf(v1, xb3.w, ac3.w);
        }
        if (e < en) {
            const unsigned long long p0 = __ldg(&g_ebuf[e]);
            const size_t ba0 = (size_t)(unsigned)(p0 & 0xffffffffu) * 32 + lane;
            const float  v0  = __uint_as_float((unsigned)(p0 >> 32));
            const float4 xa0 = __ldg(y4 + ba0);
            const float4 xa1 = __ldg(y4 + bstr + ba0);
            const float4 xa2 = __ldg(y4 + 2 * bstr + ba0);
            const float4 xa3 = __ldg(y4 + 3 * bstr + ba0);
            ac0.x = fmaf(v0, xa0.x, ac0.x); ac0.y = fmaf(v0, xa0.y, ac0.y);
            ac0.z = fmaf(v0, xa0.z, ac0.z); ac0.w = fmaf(v0, xa0.w, ac0.w);
            ac1.x = fmaf(v0, xa1.x, ac1.x); ac1.y = fmaf(v0, xa1.y, ac1.y);
            ac1.z = fmaf(v0, xa1.z, ac1.z); ac1.w = fmaf(v0, xa1.w, ac1.w);
            ac2.x = fmaf(v0, xa2.x, ac2.x); ac2.y = fmaf(v0, xa2.y, ac2.y);
            ac2.z = fmaf(v0, xa2.z, ac2.z); ac2.w = fmaf(v0, xa2.w, ac2.w);
            ac3.x = fmaf(v0, xa3.x, ac3.x); ac3.y = fmaf(v0, xa3.y, ac3.y);
            ac3.z = fmaf(v0, xa3.z, ac3.z); ac3.w = fmaf(v0, xa3.w, ac3.w);
        }

        float4* op = reinterpret_cast<float4*>(out);
        float4 r;
        r.x = fmaxf(ac0.x + bias4.x, 0.f); r.y = fmaxf(ac0.y + bias4.y, 0.f);
        r.z = fmaxf(ac0.z + bias4.z, 0.f); r.w = fmaxf(ac0.w + bias4.w, 0.f);
        op[(size_t)n * 32 + lane] = r;
        r.x = fmaxf(ac1.x + bias4.x, 0.f); r.y = fmaxf(ac1.y + bias4.y, 0.f);
        r.z = fmaxf(ac1.z + bias4.z, 0.f); r.w = fmaxf(ac1.w + bias4.w, 0.f);
        op[bstr + (size_t)n * 32 + lane] = r;
        r.x = fmaxf(ac2.x + bias4.x, 0.f); r.y = fmaxf(ac2.y + bias4.y, 0.f);
        r.z = fmaxf(ac2.z + bias4.z, 0.f); r.w = fmaxf(ac2.w + bias4.w, 0.f);
        op[2 * bstr + (size_t)n * 32 + lane] = r;
        r.x = fmaxf(ac3.x + bias4.x, 0.f); r.y = fmaxf(ac3.y + bias4.y, 0.f);
        r.z = fmaxf(ac3.z + bias4.z, 0.f); r.w = fmaxf(ac3.w + bias4.w, 0.f);
        op[3 * bstr + (size_t)n * 32 + lane] = r;
    }
}

// ---------------------------------------------------------------------------
// Launch
// ---------------------------------------------------------------------------
extern "C" void kernel_launch(void* const* d_in, const int* in_sizes, int n_in,
                              void* d_out, int out_size) {
    const float* x    = (const float*)d_in[0];
    const int*   er   = (const int*)  d_in[1];
    const int*   ec   = (const int*)  d_in[2];
    const float* ev   = (const float*)d_in[3];
    const float* W    = (const float*)d_in[4];
    const float* bias = (const float*)d_in[5];
    float*       out  = (float*)d_out;

    const int E  = in_sizes[1];
    const int C  = in_sizes[5];            // 128
    const int BN = in_sizes[0] / C;        // B*N
    const int N  = N_NODES;

    // 1) CSR build
    zero_deg_kernel<<<(N + 255) / 256, 256>>>(N);
    hist_kernel<<<(E + 255) / 256, 256>>>(er, E);
    scan_kernel<<<1, 1024>>>(N);
    scatter_kernel<<<(E + 255) / 256, 256>>>(er, ec, ev, E);

    // 2) y = x @ W
    cudaFuncSetAttribute(gemm_kernel,
                         cudaFuncAttributeMaxDynamicSharedMemorySize, 131072);
    gemm_kernel<<<(BN + 127) / 128, 256, 131072>>>(x, W, BN);

    // 3) gather + bias + relu (all batches per warp pass)
    gather_kernel<<<(N + 63) / 64, 256>>>(bias, out, N);
}

// round 7
// speedup vs baseline: 1.1459x; 1.1459x over previous
#include <cuda_runtime.h>
#include <cstdint>

// ---------------------------------------------------------------------------
// GCN layer: out = relu( (A x) @ W + b )  ==  relu( A (x@W) + b )
// R3 structure + L2-residency policy: y (102MB) is the only stream allowed to
// cache in L2; x reads, edge-record reads and out writes are evict-first.
//   1) CSR build (zero deg -> histogram -> scan -> scatter packed {col,val})
//   2) y = x @ W   (fp32x2 tiled GEMM, x via __ldcs)  -> scratch g_y
//   3) gather per (row-block, batch): out = relu(b + sum v*y[col]),
//      shfl-broadcast records (__ldcs), out via __stcs.
// ---------------------------------------------------------------------------

#define C_DIM 128
static constexpr int  N_NODES = 50000;
static constexpr int  B_MAX   = 4;
static constexpr int  E_MAX   = 800000;
static constexpr long Y_ELEMS = (long)B_MAX * N_NODES * C_DIM;

__device__ float                            g_y[Y_ELEMS];      // 102.4 MB
__device__ int                              g_deg[N_NODES];
__device__ int                              g_off[N_NODES + 1];
__device__ int                              g_cur[N_NODES];
__device__ __align__(16) unsigned long long g_ebuf[E_MAX];     // {val:hi, col:lo}

// ---------------------------------------------------------------------------
// f32x2 packed helpers
// ---------------------------------------------------------------------------
__device__ __forceinline__ unsigned long long pack2(float lo, float hi) {
    unsigned long long r;
    asm("mov.b64 %0, {%1, %2};" : "=l"(r) : "f"(lo), "f"(hi));
    return r;
}
__device__ __forceinline__ void unpack2(unsigned long long p, float& lo, float& hi) {
    asm("mov.b64 {%0, %1}, %2;" : "=f"(lo), "=f"(hi) : "l"(p));
}
__device__ __forceinline__ void fma2(unsigned long long& d,
                                     unsigned long long a,
                                     unsigned long long b) {
    asm("fma.rn.f32x2 %0, %1, %2, %0;" : "+l"(d) : "l"(a), "l"(b));
}

// ---------------------------------------------------------------------------
// CSR build
// ---------------------------------------------------------------------------
__global__ void zero_deg_kernel(int n) {
    int i = blockIdx.x * blockDim.x + threadIdx.x;
    if (i < n) g_deg[i] = 0;
}

__global__ void hist_kernel(const int* __restrict__ er, int E) {
    int e = blockIdx.x * blockDim.x + threadIdx.x;
    if (e < E) atomicAdd(&g_deg[er[e]], 1);
}

__global__ void __launch_bounds__(1024) scan_kernel(int N) {
    __shared__ int part[1024];
    const int tid   = threadIdx.x;
    const int chunk = (N + 1023) / 1024;
    const int s = tid * chunk;
    const int e = min(s + chunk, N);

    int sum = 0;
    for (int i = s; i < e; ++i) sum += g_deg[i];
    part[tid] = sum;
    __syncthreads();

    for (int ofs = 1; ofs < 1024; ofs <<= 1) {
        int v = (tid >= ofs) ? part[tid - ofs] : 0;
        __syncthreads();
        part[tid] += v;
        __syncthreads();
    }
    int run = (tid == 0) ? 0 : part[tid - 1];
    for (int i = s; i < e; ++i) {
        g_off[i] = run;
        g_cur[i] = run;
        run += g_deg[i];
    }
    if (s < N && e == N) g_off[N] = run;
}

__global__ void scatter_kernel(const int*   __restrict__ er,
                               const int*   __restrict__ ec,
                               const float* __restrict__ ev,
                               int E) {
    int e = blockIdx.x * blockDim.x + threadIdx.x;
    if (e >= E) return;
    const int pos = atomicAdd(&g_cur[er[e]], 1);
    const unsigned long long rec =
        ((unsigned long long)__float_as_uint(ev[e]) << 32) | (unsigned)ec[e];
    g_ebuf[pos] = rec;
}

// ---------------------------------------------------------------------------
// GEMM: y = x @ W   (R3 core: 128x128 CTA tile, 256 thr, 8x8 micro, fp32x2).
// x loaded with __ldcs (read-once stream, keep L2 for y).
// ---------------------------------------------------------------------------
__global__ void __launch_bounds__(256)
gemm_kernel(const float* __restrict__ x,
            const float* __restrict__ W,
            int total_rows) {
    extern __shared__ float sm[];
    float* As = sm;                 // [128][128]
    float* Ws = sm + 128 * 128;     // [128][128]

    const int  tid  = threadIdx.x;
    const long row0 = (long)blockIdx.x * 128;

    {
        const float4* Wg = reinterpret_cast<const float4*>(W);
        float4*       Wd = reinterpret_cast<float4*>(Ws);
        for (int i = tid; i < 4096; i += 256) Wd[i] = Wg[i];
    }
    {
        const float4* Ag = reinterpret_cast<const float4*>(x);
        float4*       Ad = reinterpret_cast<float4*>(As);
        for (int i = tid; i < 4096; i += 256) {
            const int  r  = i >> 5;
            const int  c4 = i & 31;
            const long gr = row0 + r;
            Ad[i] = (gr < total_rows) ? __ldcs(Ag + gr * 32 + c4)
                                      : make_float4(0.f, 0.f, 0.f, 0.f);
        }
    }
    __syncthreads();

    const int tx = tid & 15;   // cols [tx*8, tx*8+8)
    const int ty = tid >> 4;   // rows [ty*8, ty*8+8)

    unsigned long long acc[8][4];
#pragma unroll
    for (int r = 0; r < 8; ++r)
#pragma unroll
        for (int cp = 0; cp < 4; ++cp) acc[r][cp] = 0ULL;

    const float* a_base = As + ty * 8 * 128;

#pragma unroll 4
    for (int k = 0; k < 128; ++k) {
        const unsigned long long* wp =
            reinterpret_cast<const unsigned long long*>(Ws + k * 128 + tx * 8);
        const unsigned long long w0 = wp[0];
        const unsigned long long w1 = wp[1];
        const unsigned long long w2 = wp[2];
        const unsigned long long w3 = wp[3];
#pragma unroll
        for (int r = 0; r < 8; ++r) {
            const float a = a_base[r * 128 + k];
            const unsigned long long aa = pack2(a, a);
            fma2(acc[r][0], aa, w0);
            fma2(acc[r][1], aa, w1);
            fma2(acc[r][2], aa, w2);
            fma2(acc[r][3], aa, w3);
        }
    }

#pragma unroll
    for (int r = 0; r < 8; ++r) {
        const long gr = row0 + ty * 8 + r;
        if (gr >= total_rows) continue;
        float o[8];
#pragma unroll
        for (int cp = 0; cp < 4; ++cp)
            unpack2(acc[r][cp], o[2 * cp], o[2 * cp + 1]);
        float4* op = reinterpret_cast<float4*>(g_y + gr * C_DIM + tx * 8);
        op[0] = make_float4(o[0], o[1], o[2], o[3]);
        op[1] = make_float4(o[4], o[5], o[6], o[7]);
    }
}

// ---------------------------------------------------------------------------
// Gather (R3 core): out[b,n,:] = relu( bias + sum_e val_e * y[b, col_e, :] )
// One warp per row; lane owns 4 channels. Records via __ldcs + shfl. Output
// via __stcs (evict-first: do not pollute L2, keep y resident).
// ---------------------------------------------------------------------------
__global__ void __launch_bounds__(256)
gather_kernel(const float* __restrict__ bias,
              float*       __restrict__ out,
              int N) {
    const int lane = threadIdx.x & 31;
    const int warp = threadIdx.x >> 5;
    const int b    = blockIdx.y;

    const float4* yb    = reinterpret_cast<const float4*>(g_y) + (size_t)b * N * 32;
    const float4  bias4 = __ldg(reinterpret_cast<const float4*>(bias) + lane);

    const int n_base = blockIdx.x * 64;

#pragma unroll 1
    for (int i = 0; i < 8; ++i) {
        const int n = n_base + warp * 8 + i;
        if (n >= N) return;

        const int st = __ldg(&g_off[n]);
        const int en = __ldg(&g_off[n + 1]);

        float4 a0 = make_float4(0.f, 0.f, 0.f, 0.f);
        float4 a1 = make_float4(0.f, 0.f, 0.f, 0.f);

        for (int base = st; base < en; base += 32) {
            const int m = min(32, en - base);
            unsigned long long pk = 0;
            if (lane < m) pk = __ldcs(&g_ebuf[base + lane]);

            int j = 0;
            for (; j + 1 < m; j += 2) {
                const unsigned long long p0 = __shfl_sync(0xffffffffu, pk, j);
                const unsigned long long p1 = __shfl_sync(0xffffffffu, pk, j + 1);
                const int   c0 = (int)(p0 & 0xffffffffu);
                const int   c1 = (int)(p1 & 0xffffffffu);
                const float v0 = __uint_as_float((unsigned)(p0 >> 32));
                const float v1 = __uint_as_float((unsigned)(p1 >> 32));
                const float4 x0 = __ldg(yb + (size_t)c0 * 32 + lane);
                const float4 x1 = __ldg(yb + (size_t)c1 * 32 + lane);
                a0.x = fmaf(v0, x0.x, a0.x); a0.y = fmaf(v0, x0.y, a0.y);
                a0.z = fmaf(v0, x0.z, a0.z); a0.w = fmaf(v0, x0.w, a0.w);
                a1.x = fmaf(v1, x1.x, a1.x); a1.y = fmaf(v1, x1.y, a1.y);
                a1.z = fmaf(v1, x1.z, a1.z); a1.w = fmaf(v1, x1.w, a1.w);
            }
            if (j < m) {
                const unsigned long long p0 = __shfl_sync(0xffffffffu, pk, j);
                const int   c0 = (int)(p0 & 0xffffffffu);
                const float v0 = __uint_as_float((unsigned)(p0 >> 32));
                const float4 x0 = __ldg(yb + (size_t)c0 * 32 + lane);
                a0.x = fmaf(v0, x0.x, a0.x); a0.y = fmaf(v0, x0.y, a0.y);
                a0.z = fmaf(v0, x0.z, a0.z); a0.w = fmaf(v0, x0.w, a0.w);
            }
        }

        float4 r;
        r.x = fmaxf(a0.x + a1.x + bias4.x, 0.f);
        r.y = fmaxf(a0.y + a1.y + bias4.y, 0.f);
        r.z = fmaxf(a0.z + a1.z + bias4.z, 0.f);
        r.w = fmaxf(a0.w + a1.w + bias4.w, 0.f);

        __stcs(reinterpret_cast<float4*>(out) + ((size_t)b * N + n) * 32 + lane, r);
    }
}

// ---------------------------------------------------------------------------
// Launch
// ---------------------------------------------------------------------------
extern "C" void kernel_launch(void* const* d_in, const int* in_sizes, int n_in,
                              void* d_out, int out_size) {
    const float* x    = (const float*)d_in[0];
    const int*   er   = (const int*)  d_in[1];
    const int*   ec   = (const int*)  d_in[2];
    const float* ev   = (const float*)d_in[3];
    const float* W    = (const float*)d_in[4];
    const float* bias = (const float*)d_in[5];
    float*       out  = (float*)d_out;

    const int E  = in_sizes[1];
    const int C  = in_sizes[5];            // 128
    const int BN = in_sizes[0] / C;        // B*N
    const int N  = N_NODES;
    const int B  = BN / N;

    // 1) CSR build
    zero_deg_kernel<<<(N + 255) / 256, 256>>>(N);
    hist_kernel<<<(E + 255) / 256, 256>>>(er, E);
    scan_kernel<<<1, 1024>>>(N);
    scatter_kernel<<<(E + 255) / 256, 256>>>(er, ec, ev, E);

    // 2) y = x @ W
    cudaFuncSetAttribute(gemm_kernel,
                         cudaFuncAttributeMaxDynamicSharedMemorySize, 131072);
    gemm_kernel<<<(BN + 127) / 128, 256, 131072>>>(x, W, BN);

    // 3) gather + bias + relu
    dim3 ggrid((N + 63) / 64, B);
    gather_kernel<<<ggrid, 256>>>(bias, out, N);
}

// round 8
// speedup vs baseline: 1.2657x; 1.1045x over previous
#include <cuda_runtime.h>
#include <cuda_fp16.h>
#include <cstdint>

// ---------------------------------------------------------------------------
// GCN layer: out = relu( (A x) @ W + b )  ==  relu( A (x@W) + b )
// R7 structure, single change: intermediate y = x@W stored as FP16 (halves
// gather traffic + wavefronts; fp32 accumulation preserved).
//   1) CSR build (zero deg -> histogram -> scan -> scatter packed {col,val})
//   2) y = x @ W   (fp32x2 tiled GEMM, fp16 store)  -> scratch g_yh (51MB)
//   3) gather per (row-block, batch): out = relu(b + sum v*y[col]),
//      shfl-broadcast records (__ldcs), fp16->fp32 convert, out via __stcs.
// ---------------------------------------------------------------------------

#define C_DIM 128
static constexpr int  N_NODES = 50000;
static constexpr int  B_MAX   = 4;
static constexpr int  E_MAX   = 800000;
static constexpr long Y_ELEMS = (long)B_MAX * N_NODES * C_DIM;

__device__ __align__(16) __half             g_yh[Y_ELEMS];     // 51.2 MB
__device__ int                              g_deg[N_NODES];
__device__ int                              g_off[N_NODES + 1];
__device__ int                              g_cur[N_NODES];
__device__ __align__(16) unsigned long long g_ebuf[E_MAX];     // {val:hi, col:lo}

// ---------------------------------------------------------------------------
// f32x2 packed helpers
// ---------------------------------------------------------------------------
__device__ __forceinline__ unsigned long long pack2(float lo, float hi) {
    unsigned long long r;
    asm("mov.b64 %0, {%1, %2};" : "=l"(r) : "f"(lo), "f"(hi));
    return r;
}
__device__ __forceinline__ void unpack2(unsigned long long p, float& lo, float& hi) {
    asm("mov.b64 {%0, %1}, %2;" : "=f"(lo), "=f"(hi) : "l"(p));
}
__device__ __forceinline__ void fma2(unsigned long long& d,
                                     unsigned long long a,
                                     unsigned long long b) {
    asm("fma.rn.f32x2 %0, %1, %2, %0;" : "+l"(d) : "l"(a), "l"(b));
}

// ---------------------------------------------------------------------------
// CSR build
// ---------------------------------------------------------------------------
__global__ void zero_deg_kernel(int n) {
    int i = blockIdx.x * blockDim.x + threadIdx.x;
    if (i < n) g_deg[i] = 0;
}

__global__ void hist_kernel(const int* __restrict__ er, int E) {
    int e = blockIdx.x * blockDim.x + threadIdx.x;
    if (e < E) atomicAdd(&g_deg[er[e]], 1);
}

__global__ void __launch_bounds__(1024) scan_kernel(int N) {
    __shared__ int part[1024];
    const int tid   = threadIdx.x;
    const int chunk = (N + 1023) / 1024;
    const int s = tid * chunk;
    const int e = min(s + chunk, N);

    int sum = 0;
    for (int i = s; i < e; ++i) sum += g_deg[i];
    part[tid] = sum;
    __syncthreads();

    for (int ofs = 1; ofs < 1024; ofs <<= 1) {
        int v = (tid >= ofs) ? part[tid - ofs] : 0;
        __syncthreads();
        part[tid] += v;
        __syncthreads();
    }
    int run = (tid == 0) ? 0 : part[tid - 1];
    for (int i = s; i < e; ++i) {
        g_off[i] = run;
        g_cur[i] = run;
        run += g_deg[i];
    }
    if (s < N && e == N) g_off[N] = run;
}

__global__ void scatter_kernel(const int*   __restrict__ er,
                               const int*   __restrict__ ec,
                               const float* __restrict__ ev,
                               int E) {
    int e = blockIdx.x * blockDim.x + threadIdx.x;
    if (e >= E) return;
    const int pos = atomicAdd(&g_cur[er[e]], 1);
    const unsigned long long rec =
        ((unsigned long long)__float_as_uint(ev[e]) << 32) | (unsigned)ec[e];
    g_ebuf[pos] = rec;
}

// ---------------------------------------------------------------------------
// GEMM: y = x @ W   (128x128 CTA tile, 256 thr, 8x8 micro, fp32x2 core).
// x via __ldcs (read-once). Epilogue converts to fp16, one STG.128 / thread.
// ---------------------------------------------------------------------------
__global__ void __launch_bounds__(256)
gemm_kernel(const float* __restrict__ x,
            const float* __restrict__ W,
            int total_rows) {
    extern __shared__ float sm[];
    float* As = sm;                 // [128][128]
    float* Ws = sm + 128 * 128;     // [128][128]

    const int  tid  = threadIdx.x;
    const long row0 = (long)blockIdx.x * 128;

    {
        const float4* Wg = reinterpret_cast<const float4*>(W);
        float4*       Wd = reinterpret_cast<float4*>(Ws);
        for (int i = tid; i < 4096; i += 256) Wd[i] = Wg[i];
    }
    {
        const float4* Ag = reinterpret_cast<const float4*>(x);
        float4*       Ad = reinterpret_cast<float4*>(As);
        for (int i = tid; i < 4096; i += 256) {
            const int  r  = i >> 5;
            const int  c4 = i & 31;
            const long gr = row0 + r;
            Ad[i] = (gr < total_rows) ? __ldcs(Ag + gr * 32 + c4)
                                      : make_float4(0.f, 0.f, 0.f, 0.f);
        }
    }
    __syncthreads();

    const int tx = tid & 15;   // cols [tx*8, tx*8+8)
    const int ty = tid >> 4;   // rows [ty*8, ty*8+8)

    unsigned long long acc[8][4];
#pragma unroll
    for (int r = 0; r < 8; ++r)
#pragma unroll
        for (int cp = 0; cp < 4; ++cp) acc[r][cp] = 0ULL;

    const float* a_base = As + ty * 8 * 128;

#pragma unroll 4
    for (int k = 0; k < 128; ++k) {
        const unsigned long long* wp =
            reinterpret_cast<const unsigned long long*>(Ws + k * 128 + tx * 8);
        const unsigned long long w0 = wp[0];
        const unsigned long long w1 = wp[1];
        const unsigned long long w2 = wp[2];
        const unsigned long long w3 = wp[3];
#pragma unroll
        for (int r = 0; r < 8; ++r) {
            const float a = a_base[r * 128 + k];
            const unsigned long long aa = pack2(a, a);
            fma2(acc[r][0], aa, w0);
            fma2(acc[r][1], aa, w1);
            fma2(acc[r][2], aa, w2);
            fma2(acc[r][3], aa, w3);
        }
    }

#pragma unroll
    for (int r = 0; r < 8; ++r) {
        const long gr = row0 + ty * 8 + r;
        if (gr >= total_rows) continue;
        float o[8];
#pragma unroll
        for (int cp = 0; cp < 4; ++cp)
            unpack2(acc[r][cp], o[2 * cp], o[2 * cp + 1]);

        const __half2 h0 = __floats2half2_rn(o[0], o[1]);
        const __half2 h1 = __floats2half2_rn(o[2], o[3]);
        const __half2 h2 = __floats2half2_rn(o[4], o[5]);
        const __half2 h3 = __floats2half2_rn(o[6], o[7]);
        uint4 pk;
        pk.x = *reinterpret_cast<const unsigned*>(&h0);
        pk.y = *reinterpret_cast<const unsigned*>(&h1);
        pk.z = *reinterpret_cast<const unsigned*>(&h2);
        pk.w = *reinterpret_cast<const unsigned*>(&h3);
        *reinterpret_cast<uint4*>(g_yh + gr * C_DIM + tx * 8) = pk;
    }
}

// ---------------------------------------------------------------------------
// Gather: out[b,n,:] = relu( bias + sum_e val_e * y[b, col_e, :] )
// One warp per row; lane owns 4 channels (two half2 = LDG.64, 256B/warp).
// Records via __ldcs + shfl; fp32 accumulation; out via __stcs.
// ---------------------------------------------------------------------------
__global__ void __launch_bounds__(256)
gather_kernel(const float* __restrict__ bias,
              float*       __restrict__ out,
              int N) {
    const int lane = threadIdx.x & 31;
    const int warp = threadIdx.x >> 5;
    const int b    = blockIdx.y;

    const uint2* yb    = reinterpret_cast<const uint2*>(g_yh) + (size_t)b * N * 32;
    const float4 bias4 = __ldg(reinterpret_cast<const float4*>(bias) + lane);

    const int n_base = blockIdx.x * 64;

#pragma unroll 1
    for (int i = 0; i < 8; ++i) {
        const int n = n_base + warp * 8 + i;
        if (n >= N) return;

        const int st = __ldg(&g_off[n]);
        const int en = __ldg(&g_off[n + 1]);

        float4 a0 = make_float4(0.f, 0.f, 0.f, 0.f);
        float4 a1 = make_float4(0.f, 0.f, 0.f, 0.f);

        for (int base = st; base < en; base += 32) {
            const int m = min(32, en - base);
            unsigned long long pk = 0;
            if (lane < m) pk = __ldcs(&g_ebuf[base + lane]);

            int j = 0;
            for (; j + 1 < m; j += 2) {
                const unsigned long long p0 = __shfl_sync(0xffffffffu, pk, j);
                const unsigned long long p1 = __shfl_sync(0xffffffffu, pk, j + 1);
                const int   c0 = (int)(p0 & 0xffffffffu);
                const int   c1 = (int)(p1 & 0xffffffffu);
                const float v0 = __uint_as_float((unsigned)(p0 >> 32));
                const float v1 = __uint_as_float((unsigned)(p1 >> 32));
                const uint2 q0 = __ldg(yb + (size_t)c0 * 32 + lane);
                const uint2 q1 = __ldg(yb + (size_t)c1 * 32 + lane);

                const float2 f0a = __half22float2(*reinterpret_cast<const __half2*>(&q0.x));
                const float2 f0b = __half22float2(*reinterpret_cast<const __half2*>(&q0.y));
                const float2 f1a = __half22float2(*reinterpret_cast<const __half2*>(&q1.x));
                const float2 f1b = __half22float2(*reinterpret_cast<const __half2*>(&q1.y));

                a0.x = fmaf(v0, f0a.x, a0.x); a0.y = fmaf(v0, f0a.y, a0.y);
                a0.z = fmaf(v0, f0b.x, a0.z); a0.w = fmaf(v0, f0b.y, a0.w);
                a1.x = fmaf(v1, f1a.x, a1.x); a1.y = fmaf(v1, f1a.y, a1.y);
                a1.z = fmaf(v1, f1b.x, a1.z); a1.w = fmaf(v1, f1b.y, a1.w);
            }
            if (j < m) {
                const unsigned long long p0 = __shfl_sync(0xffffffffu, pk, j);
                const int   c0 = (int)(p0 & 0xffffffffu);
                const float v0 = __uint_as_float((unsigned)(p0 >> 32));
                const uint2 q0 = __ldg(yb + (size_t)c0 * 32 + lane);
                const float2 f0a = __half22float2(*reinterpret_cast<const __half2*>(&q0.x));
                const float2 f0b = __half22float2(*reinterpret_cast<const __half2*>(&q0.y));
                a0.x = fmaf(v0, f0a.x, a0.x); a0.y = fmaf(v0, f0a.y, a0.y);
                a0.z = fmaf(v0, f0b.x, a0.z); a0.w = fmaf(v0, f0b.y, a0.w);
            }
        }

        float4 r;
        r.x = fmaxf(a0.x + a1.x + bias4.x, 0.f);
        r.y = fmaxf(a0.y + a1.y + bias4.y, 0.f);
        r.z = fmaxf(a0.z + a1.z + bias4.z, 0.f);
        r.w = fmaxf(a0.w + a1.w + bias4.w, 0.f);

        __stcs(reinterpret_cast<float4*>(out) + ((size_t)b * N + n) * 32 + lane, r);
    }
}

// ---------------------------------------------------------------------------
// Launch
// ---------------------------------------------------------------------------
extern "C" void kernel_launch(void* const* d_in, const int* in_sizes, int n_in,
                              void* d_out, int out_size) {
    const float* x    = (const float*)d_in[0];
    const int*   er   = (const int*)  d_in[1];
    const int*   ec   = (const int*)  d_in[2];
    const float* ev   = (const float*)d_in[3];
    const float* W    = (const float*)d_in[4];
    const float* bias = (const float*)d_in[5];
    float*       out  = (float*)d_out;

    const int E  = in_sizes[1];
    const int C  = in_sizes[5];            // 128
    const int BN = in_sizes[0] / C;        // B*N
    const int N  = N_NODES;
    const int B  = BN / N;

    // 1) CSR build
    zero_deg_kernel<<<(N + 255) / 256, 256>>>(N);
    hist_kernel<<<(E + 255) / 256, 256>>>(er, E);
    scan_kernel<<<1, 1024>>>(N);
    scatter_kernel<<<(E + 255) / 256, 256>>>(er, ec, ev, E);

    // 2) y = x @ W  (fp16 output)
    cudaFuncSetAttribute(gemm_kernel,
                         cudaFuncAttributeMaxDynamicSharedMemorySize, 131072);
    gemm_kernel<<<(BN + 127) / 128, 256, 131072>>>(x, W, BN);

    // 3) gather + bias + relu
    dim3 ggrid((N + 63) / 64, B);
    gather_kernel<<<ggrid, 256>>>(bias, out, N);
}